// round 15
// baseline (speedup 1.0000x reference)
#include <cuda_runtime.h>
#include <cuda_fp16.h>
#include <cstdint>

// ============================================================================
// QuantizedLinear: out[1024,4096] = x @ W^T + bias
//   W[o, b*8+j] = centroids[assignments[b*4096 + o], j]
//
// fp16 mma.sync.m16n8k16 (f32 accum). R15: SINGLE fused kernel. The 296-CTA
// GEMM (2/SM on all 148 SMs, at the 12cyc/HMMA floor) produces the fp16
// operand slices ITSELF, 6 k-slices ahead of consumption, synchronized by
// per-slice arrival counters + a self-resetting global barrier. Prep cost
// (~16us serial in R13/R14) hides under the mainloop.
// ============================================================================

#define M_DIM 1024
#define N_DIM 4096
#define K_DIM 4096
#define BM 128
#define BN 112                           // 14 n8-frags; 37 tiles cover N
#define NTILE_N 37
#define N_PAD (NTILE_N * BN)             // 4144 rows in g_Bp (pad stays zero)
#define BK 64                            // 64 k per tile -> 128B fp16 rows
#define NT (K_DIM / BK)                  // 64 k-slices
#define A_BYTES (BM * 128)               // 16384
#define B_BYTES (BN * 128)               // 14336
#define STAGE_BYTES (A_BYTES + B_BYTES)  // 30720
#define SMEM_TOTAL (2 * STAGE_BYTES)     // 61440
#define THREADS 128
#define GRID_CTAS (NTILE_N * 8)          // 296 = 2 per SM on 148 SMs
#define LA 6                             // production lookahead (slices)

// fp16 operands, fragment-friendly permuted layout: row-major [row][K]; each
// 16-k block stored in order {0,1,8,9,2,3,10,11, 4,5,12,13,6,7,14,15}.
// g_Bp pad rows (>=4096) are never written; static zero-init keeps them 0.
__device__ __align__(16) __half g_Ap[(size_t)M_DIM * K_DIM];
__device__ __align__(16) __half g_Bp[(size_t)N_PAD * K_DIM];
__device__ unsigned g_done[NT];          // per-slice arrivals (reset phase 0)
__device__ unsigned g_bar_ctr;           // global barrier arrivals (self-reset)
__device__ unsigned g_bar_rel;           // monotonic release count

// ---------------------------------------------------------------------------
__device__ __forceinline__ uint32_t smem_u32(const void* p) {
    uint32_t a;
    asm("{ .reg .u64 t; cvta.to.shared.u64 t, %1; cvt.u32.u64 %0, t; }"
        : "=r"(a) : "l"(p));
    return a;
}

__device__ __forceinline__ void cp_async16(uint32_t s, const void* g) {
    asm volatile("cp.async.cg.shared.global [%0], [%1], 16;" :: "r"(s), "l"(g));
}
#define CP_COMMIT() asm volatile("cp.async.commit_group;" ::: "memory")
#define CP_WAIT0()  asm volatile("cp.async.wait_group 0;" ::: "memory")

__device__ __forceinline__ void mma_f16(float* c, const uint32_t* a, const uint32_t* b) {
    asm volatile(
        "mma.sync.aligned.m16n8k16.row.col.f32.f16.f16.f32 "
        "{%0,%1,%2,%3}, {%4,%5,%6,%7}, {%8,%9}, {%0,%1,%2,%3};"
        : "+f"(c[0]), "+f"(c[1]), "+f"(c[2]), "+f"(c[3])
        : "r"(a[0]), "r"(a[1]), "r"(a[2]), "r"(a[3]), "r"(b[0]), "r"(b[1]));
}

// ---------------------------------------------------------------------------
// Per-CTA slice production. CTA cid owns 14 W n-rows and 4 x m-rows for all
// slices. Threads 0..111: one W 16B chunk each (14 rows x 8 chunks);
// threads 112..127: one x 16-k block each (4 rows x 4 blocks).
// ---------------------------------------------------------------------------
struct Prod {
    float4 q0, q1, q2, q3;
    size_t dst;     // element (half) offset in destination array
    int    valid;   // 0 none, 1 W, 2 X
};

__device__ __forceinline__ Prod produce_load(int s, int cid, int tid,
                                             const float* __restrict__ x,
                                             const int* __restrict__ assign,
                                             const float* __restrict__ cent) {
    Prod p; p.valid = 0;
    if (tid < 112) {
        int n = cid * 14 + (tid >> 3);
        if (n < N_DIM) {
            int c = tid & 7;
            int t16 = s * 4 + (c >> 1);
            int half = c & 1;
            int ca = __ldg(assign + (size_t)(2 * t16) * N_DIM + n);
            int cb = __ldg(assign + (size_t)(2 * t16 + 1) * N_DIM + n);
            p.q0 = __ldg(reinterpret_cast<const float4*>(cent + (size_t)ca * 8 + half * 4));
            p.q1 = __ldg(reinterpret_cast<const float4*>(cent + (size_t)cb * 8 + half * 4));
            p.dst = (size_t)n * K_DIM + s * 64 + c * 8;
            p.valid = 1;
        }
    } else {
        int t = tid - 112;
        int m = cid * 4 + (t >> 2);
        if (m < M_DIM) {
            int kb = s * 4 + (t & 3);
            const float4* src = reinterpret_cast<const float4*>(
                x + (size_t)m * K_DIM + kb * 16);
            p.q0 = __ldg(src + 0); p.q1 = __ldg(src + 1);
            p.q2 = __ldg(src + 2); p.q3 = __ldg(src + 3);
            p.dst = (size_t)m * K_DIM + kb * 16;
            p.valid = 2;
        }
    }
    return p;
}

__device__ __forceinline__ void produce_store(const Prod& p) {
    if (p.valid == 1) {
        __half2 o[4];
        o[0] = __floats2half2_rn(p.q0.x, p.q0.y);
        o[1] = __floats2half2_rn(p.q1.x, p.q1.y);
        o[2] = __floats2half2_rn(p.q0.z, p.q0.w);
        o[3] = __floats2half2_rn(p.q1.z, p.q1.w);
        *reinterpret_cast<uint4*>(g_Bp + p.dst) = *reinterpret_cast<uint4*>(o);
    } else if (p.valid == 2) {
        __half2 o0[4], o1[4];
        o0[0] = __floats2half2_rn(p.q0.x, p.q0.y);
        o0[1] = __floats2half2_rn(p.q2.x, p.q2.y);
        o0[2] = __floats2half2_rn(p.q0.z, p.q0.w);
        o0[3] = __floats2half2_rn(p.q2.z, p.q2.w);
        o1[0] = __floats2half2_rn(p.q1.x, p.q1.y);
        o1[1] = __floats2half2_rn(p.q3.x, p.q3.y);
        o1[2] = __floats2half2_rn(p.q1.z, p.q1.w);
        o1[3] = __floats2half2_rn(p.q3.z, p.q3.w);
        uint4* d = reinterpret_cast<uint4*>(g_Ap + p.dst);
        d[0] = *reinterpret_cast<uint4*>(o0);
        d[1] = *reinterpret_cast<uint4*>(o1);
    }
}

// ---------------------------------------------------------------------------
// GEMM tile loader (R13): smem rows 128B; 16B-chunk swizzle c ^= (row&3)*2.
// ---------------------------------------------------------------------------
__device__ __forceinline__ void load_tile(uint32_t smem_base, int stage,
                                          const __half* __restrict__ Ab,
                                          const __half* __restrict__ Bb,
                                          int kt, int tid) {
    uint32_t sA = smem_base + stage * STAGE_BYTES;
    uint32_t sB = sA + A_BYTES;
    const __half* Ag = Ab + kt * BK;
    const __half* Bg = Bb + kt * BK;
#pragma unroll
    for (int i = 0; i < 8; i++) {            // A: 1024 16B chunks
        int c = tid + i * THREADS;
        int row = c >> 3, ck = c & 7;
        uint32_t dst = sA + row * 128 + (uint32_t)((ck ^ ((row & 3) * 2)) << 4);
        cp_async16(dst, Ag + (size_t)row * K_DIM + ck * 8);
    }
#pragma unroll
    for (int i = 0; i < 7; i++) {            // B: 896 16B chunks (112 rows)
        int c = tid + i * THREADS;
        int row = c >> 3, ck = c & 7;
        uint32_t dst = sB + row * 128 + (uint32_t)((ck ^ ((row & 3) * 2)) << 4);
        cp_async16(dst, Bg + (size_t)row * K_DIM + ck * 8);
    }
}

// ---------------------------------------------------------------------------
// Fused kernel: grid (37, 8) = 296 CTAs, 128 threads, 2 CTAs/SM (all resident).
// ---------------------------------------------------------------------------
__global__ void __launch_bounds__(THREADS, 2)
fused_kernel(const float* __restrict__ x, const int* __restrict__ assign,
             const float* __restrict__ cent, const float* __restrict__ bias,
             float* __restrict__ out) {
    extern __shared__ char dsm[];
    const uint32_t smem_base = smem_u32(dsm);
    const int tid = threadIdx.x;
    const int lane = tid & 31;
    const int wid = tid >> 5;                // 0..3
    const int gid = lane >> 2;               // 0..7
    const int tig = lane & 3;                // 0..3
    const int wm0 = (wid >> 1) * 64;         // 2 m-slots of 64
    const int wn0 = (wid & 1) * 56;          // 2 n-slots of 56
    const int m0 = blockIdx.y * BM;
    const int n0 = blockIdx.x * BN;
    const int cid = blockIdx.y * NTILE_N + blockIdx.x;   // 0..295

    // ---- Phase 0: reset per-slice counters, then global barrier ----
    if (cid == 0 && tid < NT) g_done[tid] = 0;
    __syncthreads();
    if (tid == 0) {
        __threadfence();
        unsigned r0 = atomicAdd(&g_bar_rel, 0u);
        unsigned t = atomicAdd(&g_bar_ctr, 1u);
        if (t == GRID_CTAS - 1) {
            g_bar_ctr = 0;                   // safe: all arrived, stream-serial
            __threadfence();
            atomicAdd(&g_bar_rel, 1u);
        } else {
            while (atomicAdd(&g_bar_rel, 0u) == r0) __nanosleep(64);
        }
        __threadfence();
    }
    __syncthreads();

    // ---- Prologue: produce slices 0..LA-1, publish ----
#pragma unroll
    for (int s = 0; s < LA; s += 2) {
        Prod pa = produce_load(s, cid, tid, x, assign, cent);
        Prod pb = produce_load(s + 1, cid, tid, x, assign, cent);
        produce_store(pa);
        produce_store(pb);
    }
    __syncthreads();
    if (tid == 0) {
        __threadfence();
#pragma unroll
        for (int s = 0; s < LA; s++) atomicAdd(&g_done[s], 1u);
        // wait slice 0 fully produced chip-wide
        while (atomicAdd(&g_done[0], 0u) < GRID_CTAS) __nanosleep(32);
        __threadfence();
    }
    __syncthreads();

    const __half* Ab = g_Ap + (size_t)m0 * K_DIM;
    const __half* Bb = g_Bp + (size_t)n0 * K_DIM;

    float acc[4][7][4];
#pragma unroll
    for (int mt = 0; mt < 4; mt++)
#pragma unroll
        for (int nt = 0; nt < 7; nt++)
#pragma unroll
            for (int r = 0; r < 4; r++) acc[mt][nt][r] = 0.0f;

    const uint32_t swz_x = (uint32_t)((gid & 3) * 2);
    const uint32_t sub8 = (uint32_t)((tig & 1) << 3);

    uint32_t af[2][4][4];
    uint32_t bf[2][7][2];

    #define FRAG_LOAD(B, sa, sb, kbl)                                          \
    do {                                                                       \
        const uint32_t coff =                                                  \
            (uint32_t)(((((kbl) * 2 + (tig >> 1)) ^ swz_x) << 4) | sub8);      \
        _Pragma("unroll")                                                      \
        for (int mt = 0; mt < 4; mt++) {                                       \
            int rlo = wm0 + mt * 16 + gid;                                     \
            uint2 lo = *reinterpret_cast<const uint2*>((sa) + rlo * 128 + coff); \
            uint2 hi = *reinterpret_cast<const uint2*>((sa) + (rlo + 8) * 128 + coff); \
            af[B][mt][0] = lo.x; af[B][mt][2] = lo.y;                          \
            af[B][mt][1] = hi.x; af[B][mt][3] = hi.y;                          \
        }                                                                      \
        _Pragma("unroll")                                                      \
        for (int nt = 0; nt < 7; nt++) {                                       \
            int r = wn0 + nt * 8 + gid;                                        \
            uint2 v = *reinterpret_cast<const uint2*>((sb) + r * 128 + coff);  \
            bf[B][nt][0] = v.x; bf[B][nt][1] = v.y;                            \
        }                                                                      \
    } while (0)

    // Prologue tile 0
    load_tile(smem_base, 0, Ab, Bb, 0, tid);
    CP_COMMIT();

    for (int kt = 0; kt < NT; kt++) {
        CP_WAIT0();                          // tile kt resident
        if (tid == 0 && kt + 1 < NT) {       // slice kt+1 ready chip-wide?
            while (atomicAdd(&g_done[kt + 1], 0u) < GRID_CTAS) __nanosleep(32);
            __threadfence();                 // acquire for cp.async below
        }
        __syncthreads();                     // also: prev iter's produce stores
                                             // done by all threads of this CTA
        if (tid == 0 && kt >= 1 && kt + 5 < NT) {
            __threadfence();                 // publish slice produced last iter
            atomicAdd(&g_done[kt + 5], 1u);
        }

        if (kt + 1 < NT) load_tile(smem_base, (kt + 1) & 1, Ab, Bb, kt + 1, tid);
        CP_COMMIT();

        Prod pr; pr.valid = 0;               // produce slice kt+LA (loads now,
        if (kt + LA < NT)                    //  stores after the MMA block)
            pr = produce_load(kt + LA, cid, tid, x, assign, cent);

        const char* sa = dsm + (kt & 1) * STAGE_BYTES;
        const char* sb = sa + A_BYTES;

        FRAG_LOAD(0, sa, sb, 0);             // warm kb0
#pragma unroll
        for (int kb = 0; kb < 4; kb++) {     // four 16-k blocks
            if (kb < 3) FRAG_LOAD((kb + 1) & 1, sa, sb, kb + 1);
            const int B = kb & 1;
#pragma unroll
            for (int mt = 0; mt < 4; mt++)
#pragma unroll
                for (int nt = 0; nt < 7; nt++)
                    mma_f16(acc[mt][nt], af[B][mt], bf[B][nt]);
        }

        produce_store(pr);                   // load data arrived under MMAs
    }

    // Epilogue: c0,c1 -> (row gid, cols tig*2,+1); c2,c3 -> row gid+8.
#pragma unroll
    for (int mt = 0; mt < 4; mt++) {
        int mlo = m0 + wm0 + mt * 16 + gid;
#pragma unroll
        for (int nt = 0; nt < 7; nt++) {
            int n = n0 + wn0 + nt * 8 + tig * 2;
            if (n < N_DIM) {
                float bx = __ldg(bias + n);
                float by = __ldg(bias + n + 1);
                float2 v0 = {acc[mt][nt][0] + bx, acc[mt][nt][1] + by};
                float2 v1 = {acc[mt][nt][2] + bx, acc[mt][nt][3] + by};
                *reinterpret_cast<float2*>(out + (size_t)mlo * N_DIM + n) = v0;
                *reinterpret_cast<float2*>(out + (size_t)(mlo + 8) * N_DIM + n) = v1;
            }
        }
    }
}

// ---------------------------------------------------------------------------
extern "C" void kernel_launch(void* const* d_in, const int* in_sizes, int n_in,
                              void* d_out, int out_size) {
    const float* x = nullptr;
    const float* cent = nullptr;
    const float* bias = nullptr;
    const int* assign = nullptr;
    // Inputs by element count: x=4194304, centroids=16384, bias=4096,
    // assignments=2097152, counts=2048 (unused).
    for (int i = 0; i < n_in; i++) {
        switch (in_sizes[i]) {
            case M_DIM * K_DIM:        x = (const float*)d_in[i]; break;
            case 2048 * 8:             cent = (const float*)d_in[i]; break;
            case N_DIM:                bias = (const float*)d_in[i]; break;
            case (K_DIM / 8) * N_DIM:  assign = (const int*)d_in[i]; break;
            default: break;
        }
    }

    static bool attr_done = false;
    if (!attr_done) {
        cudaFuncSetAttribute(fused_kernel,
                             cudaFuncAttributeMaxDynamicSharedMemorySize, SMEM_TOTAL);
        attr_done = true;
    }

    fused_kernel<<<dim3(NTILE_N, 8), THREADS, SMEM_TOTAL>>>(
        x, assign, cent, bias, (float*)d_out);
}